// round 8
// baseline (speedup 1.0000x reference)
#include <cuda_runtime.h>
#include <cuda_bf16.h>

// ---------------------------------------------------------------------------
// GCNRegression: 2x GCNConv(+relu) + linear head.
// N=100000, E=1.6M, F=128, H=64. edge_index arrives int32.
//
// R8 == R7 resubmitted (R7 hit a broker/container infra failure, never ran):
//  - deg+cnt fused into one red.global.add.v2.f32 on interleaved float2
//  - dis fused into scan1
//  - gemm64 fused into agg_relu epilogue (h@W2^T in-warp, W2 pair-packed smem)
//  - GEMM scalar-FMA float4 form (known good)
//  - launch order puts gemm128 4th so ncu (-s 5 -c 1) profiles it
//
// Order: zero(1) deg_hist(2) scan1(3) gemm128(4) scan2(5) scan3(6)
//        scatter(7) agg_relu_w2(8) agg_head(9)
// ---------------------------------------------------------------------------

#define NMAX 100000
#define EMAX 1600000
#define HID 64
#define SCAN_CHUNK 4096

__device__ __align__(16) float2 g_dc[NMAX];            // {deg_sum, count}
__device__ __align__(16) float  g_dis[NMAX];
__device__ __align__(16) int    g_rowptr[NMAX + 1];
__device__ __align__(16) int    g_pos[NMAX];
__device__ __align__(16) int    g_bsum[1024];
__device__ __align__(16) int    g_boff[1024];
__device__ __align__(16) float2 g_edge[EMAX];          // {src_as_float_bits, coef}
__device__ __align__(16) float  g_bufA[(size_t)NMAX * HID];
__device__ __align__(16) float  g_bufB[(size_t)NMAX * HID];

// ---- zero {deg, cnt} -------------------------------------------------------
__global__ void k_zero_dc(int n) {
    int i = blockIdx.x * blockDim.x + threadIdx.x;
    if (i < n) g_dc[i] = make_float2(0.f, 0.f);
}

// ---- weighted in-degree + histogram, one vector RED per edge ---------------
__global__ void k_deg_hist(const int* __restrict__ dst,
                           const float* __restrict__ ew, int E) {
    int e = blockIdx.x * blockDim.x + threadIdx.x;
    if (e < E) {
        int d = dst[e];
        float w = ew[e];
        asm volatile("red.global.add.v2.f32 [%0], {%1,%2};"
                     :: "l"(&g_dc[d]), "f"(w), "f"(1.0f) : "memory");
    }
}

// ---- scan phase 1 over counts (+ fused dis = rsqrt(1+deg)) -----------------
__global__ void k_scan1(int n) {
    __shared__ int ts[1024];
    int t = threadIdx.x, b = blockIdx.x;
    int base = b * SCAN_CHUNK + t * 4;
    int c[4];
#pragma unroll
    for (int r = 0; r < 4; r++) {
        if (base + r < n) {
            float2 dc = g_dc[base + r];
            c[r] = (int)dc.y;
            g_dis[base + r] = rsqrtf(1.0f + dc.x);
        } else c[r] = 0;
    }
    int s = c[0] + c[1] + c[2] + c[3];
    ts[t] = s;
    __syncthreads();
    for (int d = 1; d < 1024; d <<= 1) {
        int v = (t >= d) ? ts[t - d] : 0;
        __syncthreads();
        ts[t] += v;
        __syncthreads();
    }
    int excl = ts[t] - s;
    if (base + 0 < n) g_rowptr[base + 0] = excl;
    if (base + 1 < n) g_rowptr[base + 1] = excl + c[0];
    if (base + 2 < n) g_rowptr[base + 2] = excl + c[0] + c[1];
    if (base + 3 < n) g_rowptr[base + 3] = excl + c[0] + c[1] + c[2];
    if (t == 1023) g_bsum[b] = ts[1023];
}

// ---- scan phase 2: scan block sums (nb <= 1024) ----------------------------
__global__ void k_scan2(int nb, int n, int E) {
    __shared__ int ts[1024];
    int t = threadIdx.x;
    int v = (t < nb) ? g_bsum[t] : 0;
    ts[t] = v;
    __syncthreads();
    for (int d = 1; d < 1024; d <<= 1) {
        int u = (t >= d) ? ts[t - d] : 0;
        __syncthreads();
        ts[t] += u;
        __syncthreads();
    }
    if (t < nb) g_boff[t] = ts[t] - v;
    if (t == 0) g_rowptr[n] = E;
}

// ---- scan phase 3: add block offsets, init cursors -------------------------
__global__ void k_scan3(int n) {
    int i = blockIdx.x * blockDim.x + threadIdx.x;
    if (i < n) {
        int r = g_rowptr[i] + g_boff[i / SCAN_CHUNK];
        g_rowptr[i] = r;
        g_pos[i] = r;
    }
}

// ---- scatter edges into dst-sorted CSR order (packed meta) -----------------
__global__ void k_scatter(const int* __restrict__ src,
                          const int* __restrict__ dst,
                          const float* __restrict__ ew, int E) {
    int e = blockIdx.x * blockDim.x + threadIdx.x;
    if (e >= E) return;
    int s = src[e];
    int d = dst[e];
    int p = atomicAdd(&g_pos[d], 1);
    g_edge[p] = make_float2(__int_as_float(s), g_dis[s] * ew[e] * g_dis[d]);
}

// ---- Y[n,64] = X[n,K] @ W[64,K]^T ; scalar FMA, 4 rows/thread --------------
template <int K>
__global__ void k_gemm(const float* __restrict__ X, const float* __restrict__ W,
                       float* __restrict__ Y, int n) {
    __shared__ float Wt[K][HID + 1];
    for (int idx = threadIdx.x; idx < K * HID; idx += blockDim.x) {
        int h = idx / K;
        int k = idx - h * K;
        Wt[k][h] = W[idx];
    }
    __syncthreads();

    const int c  = threadIdx.x & 63;
    const int rs = threadIdx.x >> 6;                // 0..3
    const long long row0 = (long long)blockIdx.x * 16 + rs * 4;

    bool v[4];
    const float4* xp[4];
#pragma unroll
    for (int r = 0; r < 4; r++) {
        v[r]  = (row0 + r) < n;
        xp[r] = (const float4*)(X + (row0 + r) * K);
    }
    float acc[4] = {0.f, 0.f, 0.f, 0.f};
#pragma unroll
    for (int k = 0; k < K; k += 4) {
        float w0 = Wt[k + 0][c];
        float w1 = Wt[k + 1][c];
        float w2 = Wt[k + 2][c];
        float w3 = Wt[k + 3][c];
#pragma unroll
        for (int r = 0; r < 4; r++) {
            float4 a = v[r] ? xp[r][k >> 2] : make_float4(0.f, 0.f, 0.f, 0.f);
            acc[r] = fmaf(a.x, w0, fmaf(a.y, w1, fmaf(a.z, w2, fmaf(a.w, w3, acc[r]))));
        }
    }
#pragma unroll
    for (int r = 0; r < 4; r++)
        if (v[r]) Y[(row0 + r) * HID + c] = acc[r];
}

// ---- segmented-sum body: acc (float2/lane) over a node's edge list ---------
__device__ __forceinline__ void agg_body(const float* __restrict__ xw,
                                         int node, int lane,
                                         float& ax, float& ay) {
    int j   = g_rowptr[node];
    int end = g_rowptr[node + 1];
    for (; j + 3 < end; j += 4) {
        float2 m0 = g_edge[j],     m1 = g_edge[j + 1];
        float2 m2 = g_edge[j + 2], m3 = g_edge[j + 3];
        int s0 = __float_as_int(m0.x), s1 = __float_as_int(m1.x);
        int s2 = __float_as_int(m2.x), s3 = __float_as_int(m3.x);
        float2 v0 = __ldg((const float2*)(xw + (size_t)s0 * HID) + lane);
        float2 v1 = __ldg((const float2*)(xw + (size_t)s1 * HID) + lane);
        float2 v2 = __ldg((const float2*)(xw + (size_t)s2 * HID) + lane);
        float2 v3 = __ldg((const float2*)(xw + (size_t)s3 * HID) + lane);
        ax = fmaf(m0.y, v0.x, ax); ay = fmaf(m0.y, v0.y, ay);
        ax = fmaf(m1.y, v1.x, ax); ay = fmaf(m1.y, v1.y, ay);
        ax = fmaf(m2.y, v2.x, ax); ay = fmaf(m2.y, v2.y, ay);
        ax = fmaf(m3.y, v3.x, ax); ay = fmaf(m3.y, v3.y, ay);
    }
    for (; j < end; j++) {
        float2 m = g_edge[j];
        int s = __float_as_int(m.x);
        float2 v = __ldg((const float2*)(xw + (size_t)s * HID) + lane);
        ax = fmaf(m.y, v.x, ax); ay = fmaf(m.y, v.y, ay);
    }
}

// ---- layer1 agg + relu, FUSED with xw2 = h @ W2^T --------------------------
// 1 warp/node. W2 pair-packed in smem: W2p[k][l] = {W2[2l][k], W2[2l+1][k]}
// so lane l's LDS.64 is conflict-free. h broadcast via per-warp smem row.
__global__ __launch_bounds__(256) void k_agg_relu_w2(
        const float* __restrict__ xw, const float* __restrict__ W2,
        const float* __restrict__ b, float* __restrict__ out, int n) {
    __shared__ float2 W2p[HID][32];
    __shared__ float  hs[8][HID];
    for (int idx = threadIdx.x; idx < HID * 32; idx += blockDim.x) {
        int k = idx >> 5;
        int l = idx & 31;
        W2p[k][l] = make_float2(W2[(2 * l) * HID + k], W2[(2 * l + 1) * HID + k]);
    }
    __syncthreads();

    int node = (blockIdx.x * blockDim.x + threadIdx.x) >> 5;
    int wrp  = (threadIdx.x >> 5);
    int lane = threadIdx.x & 31;
    if (node >= n) return;

    float ax = 0.f, ay = 0.f;
    agg_body(xw, node, lane, ax, ay);

    float ds = g_dis[node];
    float d2 = ds * ds;
    float2 xv = __ldg((const float2*)(xw + (size_t)node * HID) + lane);
    float2 bb = __ldg((const float2*)b + lane);
    float h0 = fmaxf(fmaf(d2, xv.x, ax) + bb.x, 0.f);
    float h1 = fmaxf(fmaf(d2, xv.y, ay) + bb.y, 0.f);

    // stage h for in-warp broadcast
    hs[wrp][2 * lane]     = h0;
    hs[wrp][2 * lane + 1] = h1;
    __syncwarp();

    // y[2l], y[2l+1] = sum_k h[k] * W2[{2l,2l+1}][k]
    float y0 = 0.f, y1 = 0.f;
    const float2* hrow = (const float2*)hs[wrp];
#pragma unroll
    for (int t = 0; t < 32; t++) {
        float2 hh = hrow[t];                 // {h[2t], h[2t+1]} broadcast
        float2 wa = W2p[2 * t][lane];
        float2 wb = W2p[2 * t + 1][lane];
        y0 = fmaf(hh.x, wa.x, fmaf(hh.y, wb.x, y0));
        y1 = fmaf(hh.x, wa.y, fmaf(hh.y, wb.y, y1));
    }
    ((float2*)(out + (size_t)node * HID))[lane] = make_float2(y0, y1);
}

// ---- final aggregation + relu + head dot W3 (1 warp/node) ------------------
__global__ void k_agg_head(const float* __restrict__ xw,
                           const float* __restrict__ b2,
                           const float* __restrict__ W3,
                           const float* __restrict__ b3,
                           float* __restrict__ out, int n) {
    int node = (blockIdx.x * blockDim.x + threadIdx.x) >> 5;
    int lane = threadIdx.x & 31;
    if (node >= n) return;
    float ax = 0.f, ay = 0.f;
    agg_body(xw, node, lane, ax, ay);
    float ds = g_dis[node];
    float d2 = ds * ds;
    float2 xv = __ldg((const float2*)(xw + (size_t)node * HID) + lane);
    float2 bb = __ldg((const float2*)b2 + lane);
    float h0 = fmaxf(fmaf(d2, xv.x, ax) + bb.x, 0.f);
    float h1 = fmaxf(fmaf(d2, xv.y, ay) + bb.y, 0.f);
    float2 w = __ldg((const float2*)W3 + lane);
    float sum = fmaf(h0, w.x, h1 * w.y);
#pragma unroll
    for (int off = 16; off; off >>= 1)
        sum += __shfl_xor_sync(0xffffffffu, sum, off);
    if (lane == 0) out[node] = sum + b3[0];
}

extern "C" void kernel_launch(void* const* d_in, const int* in_sizes, int n_in,
                              void* d_out, int out_size) {
    const float* x   = (const float*)d_in[0];
    const int*   ei  = (const int*)d_in[1];       // int32 (JAX x64 disabled)
    const float* ew  = (const float*)d_in[2];
    // d_in[3] = batch (unused)
    const float* W1  = (const float*)d_in[4];
    const float* b1  = (const float*)d_in[5];
    const float* W2  = (const float*)d_in[6];
    const float* b2  = (const float*)d_in[7];
    const float* W3  = (const float*)d_in[8];
    const float* b3  = (const float*)d_in[9];
    float*       out = (float*)d_out;

    const int n = in_sizes[0] / 128;   // 100000
    const int E = in_sizes[1] / 2;     // 1600000
    const int* src = ei;
    const int* dst = ei + E;

    float *dA, *dB;
    cudaGetSymbolAddress((void**)&dA, g_bufA);
    cudaGetSymbolAddress((void**)&dB, g_bufB);

    const int TB = 256;
    const int NB = (n + SCAN_CHUNK - 1) / SCAN_CHUNK;

    // single stream; gemm128 deliberately placed 4th (ncu samples launch #4)
    k_zero_dc<<<(n + TB - 1) / TB, TB>>>(n);                      // 1
    k_deg_hist<<<(E + TB - 1) / TB, TB>>>(dst, ew, E);            // 2
    k_scan1<<<NB, 1024>>>(n);                                     // 3
    k_gemm<128><<<(n + 15) / 16, TB>>>(x, W1, dA, n);             // 4  <- profiled
    k_scan2<<<1, 1024>>>(NB, n, E);                               // 5
    k_scan3<<<(n + TB - 1) / TB, TB>>>(n);                        // 6
    k_scatter<<<(E + TB - 1) / TB, TB>>>(src, dst, ew, E);        // 7
    k_agg_relu_w2<<<(n * 32 + TB - 1) / TB, TB>>>(dA, W2, b1, dB, n); // 8
    k_agg_head<<<(n * 32 + TB - 1) / TB, TB>>>(dB, b2, W3, b3, out, n); // 9
}

// round 9
// speedup vs baseline: 1.7421x; 1.7421x over previous
#include <cuda_runtime.h>
#include <cuda_bf16.h>

// ---------------------------------------------------------------------------
// GCNRegression: 2x GCNConv(+relu) + linear head.
// N=100000, E=1.6M, F=128, H=64. edge_index arrives int32.
//
// R9: - revert R8's agg+W2 fusion (that bundle regressed +159us)
//     - GEMM rebuilt: smem-staged X tile (coalesced LDG.128) + broadcast
//       LDS.128 reads; kills the uniform-LDG L1-wavefront bottleneck that
//       ncu showed (L1=91.2% SOL, 140.8us)
//     - keep: RED.v2 deg+cnt histogram, dis fused into scan1, packed edge
//       meta, CSR segmented aggregation
//     - launch order keeps gemm128 4th (ncu profiles launch #4)
//
// Order: zero(1) hist(2) scan1(3) gemm128(4) scan2(5) scan3(6) scatter(7)
//        agg_relu(8) gemm64(9) agg_head(10)
// ---------------------------------------------------------------------------

#define NMAX 100000
#define EMAX 1600000
#define HID 64
#define SCAN_CHUNK 4096

__device__ __align__(16) float2 g_dc[NMAX];            // {deg_sum, count}
__device__ __align__(16) float  g_dis[NMAX];
__device__ __align__(16) int    g_rowptr[NMAX + 1];
__device__ __align__(16) int    g_pos[NMAX];
__device__ __align__(16) int    g_bsum[1024];
__device__ __align__(16) int    g_boff[1024];
__device__ __align__(16) float2 g_edge[EMAX];          // {src_as_float_bits, coef}
__device__ __align__(16) float  g_bufA[(size_t)NMAX * HID];
__device__ __align__(16) float  g_bufB[(size_t)NMAX * HID];

// ---- zero {deg, cnt} -------------------------------------------------------
__global__ void k_zero_dc(int n) {
    int i = blockIdx.x * blockDim.x + threadIdx.x;
    if (i < n) g_dc[i] = make_float2(0.f, 0.f);
}

// ---- weighted in-degree + histogram, one vector RED per edge ---------------
__global__ void k_deg_hist(const int* __restrict__ dst,
                           const float* __restrict__ ew, int E) {
    int e = blockIdx.x * blockDim.x + threadIdx.x;
    if (e < E) {
        int d = dst[e];
        float w = ew[e];
        asm volatile("red.global.add.v2.f32 [%0], {%1,%2};"
                     :: "l"(&g_dc[d]), "f"(w), "f"(1.0f) : "memory");
    }
}

// ---- scan phase 1 over counts (+ fused dis = rsqrt(1+deg)) -----------------
__global__ void k_scan1(int n) {
    __shared__ int ts[1024];
    int t = threadIdx.x, b = blockIdx.x;
    int base = b * SCAN_CHUNK + t * 4;
    int c[4];
#pragma unroll
    for (int r = 0; r < 4; r++) {
        if (base + r < n) {
            float2 dc = g_dc[base + r];
            c[r] = (int)dc.y;
            g_dis[base + r] = rsqrtf(1.0f + dc.x);
        } else c[r] = 0;
    }
    int s = c[0] + c[1] + c[2] + c[3];
    ts[t] = s;
    __syncthreads();
    for (int d = 1; d < 1024; d <<= 1) {
        int v = (t >= d) ? ts[t - d] : 0;
        __syncthreads();
        ts[t] += v;
        __syncthreads();
    }
    int excl = ts[t] - s;
    if (base + 0 < n) g_rowptr[base + 0] = excl;
    if (base + 1 < n) g_rowptr[base + 1] = excl + c[0];
    if (base + 2 < n) g_rowptr[base + 2] = excl + c[0] + c[1];
    if (base + 3 < n) g_rowptr[base + 3] = excl + c[0] + c[1] + c[2];
    if (t == 1023) g_bsum[b] = ts[1023];
}

// ---- scan phase 2: scan block sums (nb <= 1024) ----------------------------
__global__ void k_scan2(int nb, int n, int E) {
    __shared__ int ts[1024];
    int t = threadIdx.x;
    int v = (t < nb) ? g_bsum[t] : 0;
    ts[t] = v;
    __syncthreads();
    for (int d = 1; d < 1024; d <<= 1) {
        int u = (t >= d) ? ts[t - d] : 0;
        __syncthreads();
        ts[t] += u;
        __syncthreads();
    }
    if (t < nb) g_boff[t] = ts[t] - v;
    if (t == 0) g_rowptr[n] = E;
}

// ---- scan phase 3: add block offsets, init cursors -------------------------
__global__ void k_scan3(int n) {
    int i = blockIdx.x * blockDim.x + threadIdx.x;
    if (i < n) {
        int r = g_rowptr[i] + g_boff[i / SCAN_CHUNK];
        g_rowptr[i] = r;
        g_pos[i] = r;
    }
}

// ---- scatter edges into dst-sorted CSR order (packed meta) -----------------
__global__ void k_scatter(const int* __restrict__ src,
                          const int* __restrict__ dst,
                          const float* __restrict__ ew, int E) {
    int e = blockIdx.x * blockDim.x + threadIdx.x;
    if (e >= E) return;
    int s = src[e];
    int d = dst[e];
    int p = atomicAdd(&g_pos[d], 1);
    g_edge[p] = make_float2(__int_as_float(s), g_dis[s] * ew[e] * g_dis[d]);
}

// ---- Y[n,64] = X[n,K] @ W[64,K]^T ; smem-staged X tile ---------------------
// 256 thr, 16 rows/block. X tile loaded coalesced (LDG.128) into smem once;
// inner loop reads x via broadcast LDS.128 (warp-uniform) and w via
// conflict-free scalar LDS. Per warp-k4-step: 8 LDS wavefronts, 16 FFMA.
template <int K>
__global__ __launch_bounds__(256) void k_gemm(
        const float* __restrict__ X, const float* __restrict__ W,
        float* __restrict__ Y, int n) {
    __shared__ float4 Xs4[16][K / 4];
    __shared__ float  Wt[K][HID + 1];

    // stage W transposed (padded rows -> conflict-free scatter writes)
    for (int idx = threadIdx.x; idx < K * HID; idx += blockDim.x) {
        int h = idx / K;
        int k = idx - h * K;
        Wt[k][h] = W[idx];
    }
    // stage X tile, fully coalesced
    const int row0 = blockIdx.x * 16;
    const float4* X4 = (const float4*)X;
#pragma unroll
    for (int idx = threadIdx.x; idx < 16 * (K / 4); idx += blockDim.x) {
        int r = idx / (K / 4);
        int q = idx - r * (K / 4);
        Xs4[r][q] = (row0 + r < n) ? X4[(size_t)(row0 + r) * (K / 4) + q]
                                   : make_float4(0.f, 0.f, 0.f, 0.f);
    }
    __syncthreads();

    const int c  = threadIdx.x & 63;
    const int rs = threadIdx.x >> 6;                // 0..3 -> rows rs*4..rs*4+3
    float acc[4] = {0.f, 0.f, 0.f, 0.f};
#pragma unroll
    for (int k = 0; k < K; k += 4) {
        float w0 = Wt[k + 0][c];
        float w1 = Wt[k + 1][c];
        float w2 = Wt[k + 2][c];
        float w3 = Wt[k + 3][c];
#pragma unroll
        for (int r = 0; r < 4; r++) {
            float4 a = Xs4[rs * 4 + r][k >> 2];     // broadcast within warp
            acc[r] = fmaf(a.x, w0, fmaf(a.y, w1, fmaf(a.z, w2, fmaf(a.w, w3, acc[r]))));
        }
    }
#pragma unroll
    for (int r = 0; r < 4; r++) {
        int row = row0 + rs * 4 + r;
        if (row < n) Y[(size_t)row * HID + c] = acc[r];
    }
}

// ---- segmented-sum body: acc (float2/lane) over a node's edge list ---------
__device__ __forceinline__ void agg_body(const float* __restrict__ xw,
                                         int node, int lane,
                                         float& ax, float& ay) {
    int j   = g_rowptr[node];
    int end = g_rowptr[node + 1];
    for (; j + 3 < end; j += 4) {
        float2 m0 = g_edge[j],     m1 = g_edge[j + 1];
        float2 m2 = g_edge[j + 2], m3 = g_edge[j + 3];
        int s0 = __float_as_int(m0.x), s1 = __float_as_int(m1.x);
        int s2 = __float_as_int(m2.x), s3 = __float_as_int(m3.x);
        float2 v0 = __ldg((const float2*)(xw + (size_t)s0 * HID) + lane);
        float2 v1 = __ldg((const float2*)(xw + (size_t)s1 * HID) + lane);
        float2 v2 = __ldg((const float2*)(xw + (size_t)s2 * HID) + lane);
        float2 v3 = __ldg((const float2*)(xw + (size_t)s3 * HID) + lane);
        ax = fmaf(m0.y, v0.x, ax); ay = fmaf(m0.y, v0.y, ay);
        ax = fmaf(m1.y, v1.x, ax); ay = fmaf(m1.y, v1.y, ay);
        ax = fmaf(m2.y, v2.x, ax); ay = fmaf(m2.y, v2.y, ay);
        ax = fmaf(m3.y, v3.x, ax); ay = fmaf(m3.y, v3.y, ay);
    }
    for (; j < end; j++) {
        float2 m = g_edge[j];
        int s = __float_as_int(m.x);
        float2 v = __ldg((const float2*)(xw + (size_t)s * HID) + lane);
        ax = fmaf(m.y, v.x, ax); ay = fmaf(m.y, v.y, ay);
    }
}

// ---- layer aggregation + self-loop + bias + relu (1 warp/node) -------------
__global__ void k_agg_relu(const float* __restrict__ xw,
                           const float* __restrict__ b,
                           float* __restrict__ out, int n) {
    int node = (blockIdx.x * blockDim.x + threadIdx.x) >> 5;
    int lane = threadIdx.x & 31;
    if (node >= n) return;
    float ax = 0.f, ay = 0.f;
    agg_body(xw, node, lane, ax, ay);
    float ds = g_dis[node];
    float d2 = ds * ds;
    float2 xv = __ldg((const float2*)(xw + (size_t)node * HID) + lane);
    float2 bb = __ldg((const float2*)b + lane);
    float2 r;
    r.x = fmaxf(fmaf(d2, xv.x, ax) + bb.x, 0.f);
    r.y = fmaxf(fmaf(d2, xv.y, ay) + bb.y, 0.f);
    ((float2*)(out + (size_t)node * HID))[lane] = r;
}

// ---- final aggregation + relu + head dot W3 (1 warp/node) ------------------
__global__ void k_agg_head(const float* __restrict__ xw,
                           const float* __restrict__ b2,
                           const float* __restrict__ W3,
                           const float* __restrict__ b3,
                           float* __restrict__ out, int n) {
    int node = (blockIdx.x * blockDim.x + threadIdx.x) >> 5;
    int lane = threadIdx.x & 31;
    if (node >= n) return;
    float ax = 0.f, ay = 0.f;
    agg_body(xw, node, lane, ax, ay);
    float ds = g_dis[node];
    float d2 = ds * ds;
    float2 xv = __ldg((const float2*)(xw + (size_t)node * HID) + lane);
    float2 bb = __ldg((const float2*)b2 + lane);
    float h0 = fmaxf(fmaf(d2, xv.x, ax) + bb.x, 0.f);
    float h1 = fmaxf(fmaf(d2, xv.y, ay) + bb.y, 0.f);
    float2 w = __ldg((const float2*)W3 + lane);
    float sum = fmaf(h0, w.x, h1 * w.y);
#pragma unroll
    for (int off = 16; off; off >>= 1)
        sum += __shfl_xor_sync(0xffffffffu, sum, off);
    if (lane == 0) out[node] = sum + b3[0];
}

extern "C" void kernel_launch(void* const* d_in, const int* in_sizes, int n_in,
                              void* d_out, int out_size) {
    const float* x   = (const float*)d_in[0];
    const int*   ei  = (const int*)d_in[1];       // int32 (JAX x64 disabled)
    const float* ew  = (const float*)d_in[2];
    // d_in[3] = batch (unused)
    const float* W1  = (const float*)d_in[4];
    const float* b1  = (const float*)d_in[5];
    const float* W2  = (const float*)d_in[6];
    const float* b2  = (const float*)d_in[7];
    const float* W3  = (const float*)d_in[8];
    const float* b3  = (const float*)d_in[9];
    float*       out = (float*)d_out;

    const int n = in_sizes[0] / 128;   // 100000
    const int E = in_sizes[1] / 2;     // 1600000
    const int* src = ei;
    const int* dst = ei + E;

    float *dA, *dB;
    cudaGetSymbolAddress((void**)&dA, g_bufA);
    cudaGetSymbolAddress((void**)&dB, g_bufB);

    const int TB = 256;
    const int NB = (n + SCAN_CHUNK - 1) / SCAN_CHUNK;

    // single stream; gemm128 4th (ncu profiles launch #4)
    k_zero_dc<<<(n + TB - 1) / TB, TB>>>(n);                      // 1
    k_deg_hist<<<(E + TB - 1) / TB, TB>>>(dst, ew, E);            // 2
    k_scan1<<<NB, 1024>>>(n);                                     // 3
    k_gemm<128><<<(n + 15) / 16, TB>>>(x, W1, dA, n);             // 4  <- profiled
    k_scan2<<<1, 1024>>>(NB, n, E);                               // 5
    k_scan3<<<(n + TB - 1) / TB, TB>>>(n);                        // 6
    k_scatter<<<(E + TB - 1) / TB, TB>>>(src, dst, ew, E);        // 7
    k_agg_relu<<<(n * 32 + TB - 1) / TB, TB>>>(dA, b1, dB, n);    // 8
    k_gemm<64><<<(n + 15) / 16, TB>>>(dB, W2, dA, n);             // 9
    k_agg_head<<<(n * 32 + TB - 1) / TB, TB>>>(dA, b2, W3, b3, out, n); // 10
}

// round 10
// speedup vs baseline: 2.2447x; 1.2885x over previous
#include <cuda_runtime.h>
#include <cuda_bf16.h>

// ---------------------------------------------------------------------------
// GCNRegression: 2x GCNConv(+relu) + linear head.
// N=100000, E=1.6M, F=128, H=64. edge_index arrives int32.
//
// R10: GEMM rebuilt as 4x4 register-tiled (64x64 block tile, K chunked by 64).
//      Per k4-step: 8 LDS.128 feed 64 FMAs (was 8 LDS per 16 FMAs) -> FFMA
//      becomes the binding pipe instead of L1 (ncu R9: L1=84.5%, fma=27.3%).
//      Everything else identical to R9 (best known).
//
// Order: zero(1) hist(2) scan1(3) gemm128(4) scan2(5) scan3(6) scatter(7)
//        agg_relu(8) gemm64(9) agg_head(10)
// ---------------------------------------------------------------------------

#define NMAX 100000
#define EMAX 1600000
#define HID 64
#define SCAN_CHUNK 4096

__device__ __align__(16) float2 g_dc[NMAX];            // {deg_sum, count}
__device__ __align__(16) float  g_dis[NMAX];
__device__ __align__(16) int    g_rowptr[NMAX + 1];
__device__ __align__(16) int    g_pos[NMAX];
__device__ __align__(16) int    g_bsum[1024];
__device__ __align__(16) int    g_boff[1024];
__device__ __align__(16) float2 g_edge[EMAX];          // {src_as_float_bits, coef}
__device__ __align__(16) float  g_bufA[(size_t)NMAX * HID];
__device__ __align__(16) float  g_bufB[(size_t)NMAX * HID];

// ---- zero {deg, cnt} -------------------------------------------------------
__global__ void k_zero_dc(int n) {
    int i = blockIdx.x * blockDim.x + threadIdx.x;
    if (i < n) g_dc[i] = make_float2(0.f, 0.f);
}

// ---- weighted in-degree + histogram, one vector RED per edge ---------------
__global__ void k_deg_hist(const int* __restrict__ dst,
                           const float* __restrict__ ew, int E) {
    int e = blockIdx.x * blockDim.x + threadIdx.x;
    if (e < E) {
        int d = dst[e];
        float w = ew[e];
        asm volatile("red.global.add.v2.f32 [%0], {%1,%2};"
                     :: "l"(&g_dc[d]), "f"(w), "f"(1.0f) : "memory");
    }
}

// ---- scan phase 1 over counts (+ fused dis = rsqrt(1+deg)) -----------------
__global__ void k_scan1(int n) {
    __shared__ int ts[1024];
    int t = threadIdx.x, b = blockIdx.x;
    int base = b * SCAN_CHUNK + t * 4;
    int c[4];
#pragma unroll
    for (int r = 0; r < 4; r++) {
        if (base + r < n) {
            float2 dc = g_dc[base + r];
            c[r] = (int)dc.y;
            g_dis[base + r] = rsqrtf(1.0f + dc.x);
        } else c[r] = 0;
    }
    int s = c[0] + c[1] + c[2] + c[3];
    ts[t] = s;
    __syncthreads();
    for (int d = 1; d < 1024; d <<= 1) {
        int v = (t >= d) ? ts[t - d] : 0;
        __syncthreads();
        ts[t] += v;
        __syncthreads();
    }
    int excl = ts[t] - s;
    if (base + 0 < n) g_rowptr[base + 0] = excl;
    if (base + 1 < n) g_rowptr[base + 1] = excl + c[0];
    if (base + 2 < n) g_rowptr[base + 2] = excl + c[0] + c[1];
    if (base + 3 < n) g_rowptr[base + 3] = excl + c[0] + c[1] + c[2];
    if (t == 1023) g_bsum[b] = ts[1023];
}

// ---- scan phase 2: scan block sums (nb <= 1024) ----------------------------
__global__ void k_scan2(int nb, int n, int E) {
    __shared__ int ts[1024];
    int t = threadIdx.x;
    int v = (t < nb) ? g_bsum[t] : 0;
    ts[t] = v;
    __syncthreads();
    for (int d = 1; d < 1024; d <<= 1) {
        int u = (t >= d) ? ts[t - d] : 0;
        __syncthreads();
        ts[t] += u;
        __syncthreads();
    }
    if (t < nb) g_boff[t] = ts[t] - v;
    if (t == 0) g_rowptr[n] = E;
}

// ---- scan phase 3: add block offsets, init cursors -------------------------
__global__ void k_scan3(int n) {
    int i = blockIdx.x * blockDim.x + threadIdx.x;
    if (i < n) {
        int r = g_rowptr[i] + g_boff[i / SCAN_CHUNK];
        g_rowptr[i] = r;
        g_pos[i] = r;
    }
}

// ---- scatter edges into dst-sorted CSR order (packed meta) -----------------
__global__ void k_scatter(const int* __restrict__ src,
                          const int* __restrict__ dst,
                          const float* __restrict__ ew, int E) {
    int e = blockIdx.x * blockDim.x + threadIdx.x;
    if (e >= E) return;
    int s = src[e];
    int d = dst[e];
    int p = atomicAdd(&g_pos[d], 1);
    g_edge[p] = make_float2(__int_as_float(s), g_dis[s] * ew[e] * g_dis[d]);
}

// ---- packed helper: a += s * w (float4 lanewise) ---------------------------
__device__ __forceinline__ void fma4(float4& a, float s, const float4 w) {
    a.x = fmaf(s, w.x, a.x);
    a.y = fmaf(s, w.y, a.y);
    a.z = fmaf(s, w.z, a.z);
    a.w = fmaf(s, w.w, a.w);
}

// ---- Y[n,64] = X[n,K] @ W[64,K]^T ; 4x4 register tiling --------------------
// 256 thr = 16x16 thread grid; block tile 64 rows x 64 cols; K chunked by 64.
// Per k4-step/thread: 4 broadcast LDS.128 (x) + 4 LDS.128 (w) feed 64 FMAs.
template <int K>
__global__ __launch_bounds__(256) void k_gemm(
        const float* __restrict__ X, const float* __restrict__ W,
        float* __restrict__ Y, int n) {
    __shared__ float4 Xs4[64][16];          // 16 KB: 64 rows x 64 k (chunk)
    __shared__ float  Wt[64][HID + 4];      // 17 KB: Wt[k][c], +4 pad keeps
                                            //        &Wt[k][4*tc] 16B-aligned
    const int tid  = threadIdx.x;
    const int row0 = blockIdx.x * 64;
    const int r0   = (tid >> 4) * 4;        // thread-row * 4
    const int c0   = (tid & 15) * 4;        // thread-col * 4

    const float4* X4 = (const float4*)X;

    float4 acc0 = make_float4(0.f, 0.f, 0.f, 0.f);
    float4 acc1 = acc0, acc2 = acc0, acc3 = acc0;

    for (int kc = 0; kc < K; kc += 64) {
        if (kc) __syncthreads();
        // stage X chunk: 64 rows x 16 float4, coalesced
#pragma unroll
        for (int i = 0; i < 4; i++) {
            int idx = tid + i * 256;
            int r = idx >> 4, q = idx & 15;
            int row = row0 + r;
            Xs4[r][q] = (row < n) ? X4[(size_t)row * (K / 4) + (kc >> 2) + q]
                                  : make_float4(0.f, 0.f, 0.f, 0.f);
        }
        // stage W chunk transposed: Wt[k][c] = W[c*K + kc + k] (coalesced in k)
#pragma unroll
        for (int i = 0; i < 16; i++) {
            int idx = tid + i * 256;
            int c = idx >> 6, k = idx & 63;
            Wt[k][c] = W[(size_t)c * K + kc + k];
        }
        __syncthreads();

#pragma unroll
        for (int t = 0; t < 16; t++) {
            float4 x0 = Xs4[r0 + 0][t];
            float4 x1 = Xs4[r0 + 1][t];
            float4 x2 = Xs4[r0 + 2][t];
            float4 x3 = Xs4[r0 + 3][t];
            float4 w0 = *(const float4*)&Wt[4 * t + 0][c0];
            float4 w1 = *(const float4*)&Wt[4 * t + 1][c0];
            float4 w2 = *(const float4*)&Wt[4 * t + 2][c0];
            float4 w3 = *(const float4*)&Wt[4 * t + 3][c0];
            fma4(acc0, x0.x, w0); fma4(acc0, x0.y, w1); fma4(acc0, x0.z, w2); fma4(acc0, x0.w, w3);
            fma4(acc1, x1.x, w0); fma4(acc1, x1.y, w1); fma4(acc1, x1.z, w2); fma4(acc1, x1.w, w3);
            fma4(acc2, x2.x, w0); fma4(acc2, x2.y, w1); fma4(acc2, x2.z, w2); fma4(acc2, x2.w, w3);
            fma4(acc3, x3.x, w0); fma4(acc3, x3.y, w1); fma4(acc3, x3.z, w2); fma4(acc3, x3.w, w3);
        }
    }

    const int tc = tid & 15;
#pragma unroll
    for (int i = 0; i < 4; i++) {
        int row = row0 + r0 + i;
        if (row < n) {
            float4 a = (i == 0) ? acc0 : (i == 1) ? acc1 : (i == 2) ? acc2 : acc3;
            ((float4*)(Y + (size_t)row * HID))[tc] = a;
        }
    }
}

// ---- segmented-sum body: acc (float2/lane) over a node's edge list ---------
__device__ __forceinline__ void agg_body(const float* __restrict__ xw,
                                         int node, int lane,
                                         float& ax, float& ay) {
    int j   = g_rowptr[node];
    int end = g_rowptr[node + 1];
    for (; j + 3 < end; j += 4) {
        float2 m0 = g_edge[j],     m1 = g_edge[j + 1];
        float2 m2 = g_edge[j + 2], m3 = g_edge[j + 3];
        int s0 = __float_as_int(m0.x), s1 = __float_as_int(m1.x);
        int s2 = __float_as_int(m2.x), s3 = __float_as_int(m3.x);
        float2 v0 = __ldg((const float2*)(xw + (size_t)s0 * HID) + lane);
        float2 v1 = __ldg((const float2*)(xw + (size_t)s1 * HID) + lane);
        float2 v2 = __ldg((const float2*)(xw + (size_t)s2 * HID) + lane);
        float2 v3 = __ldg((const float2*)(xw + (size_t)s3 * HID) + lane);
        ax = fmaf(m0.y, v0.x, ax); ay = fmaf(m0.y, v0.y, ay);
        ax = fmaf(m1.y, v1.x, ax); ay = fmaf(m1.y, v1.y, ay);
        ax = fmaf(m2.y, v2.x, ax); ay = fmaf(m2.y, v2.y, ay);
        ax = fmaf(m3.y, v3.x, ax); ay = fmaf(m3.y, v3.y, ay);
    }
    for (; j < end; j++) {
        float2 m = g_edge[j];
        int s = __float_as_int(m.x);
        float2 v = __ldg((const float2*)(xw + (size_t)s * HID) + lane);
        ax = fmaf(m.y, v.x, ax); ay = fmaf(m.y, v.y, ay);
    }
}

// ---- layer aggregation + self-loop + bias + relu (1 warp/node) -------------
__global__ void k_agg_relu(const float* __restrict__ xw,
                           const float* __restrict__ b,
                           float* __restrict__ out, int n) {
    int node = (blockIdx.x * blockDim.x + threadIdx.x) >> 5;
    int lane = threadIdx.x & 31;
    if (node >= n) return;
    float ax = 0.f, ay = 0.f;
    agg_body(xw, node, lane, ax, ay);
    float ds = g_dis[node];
    float d2 = ds * ds;
    float2 xv = __ldg((const float2*)(xw + (size_t)node * HID) + lane);
    float2 bb = __ldg((const float2*)b + lane);
    float2 r;
    r.x = fmaxf(fmaf(d2, xv.x, ax) + bb.x, 0.f);
    r.y = fmaxf(fmaf(d2, xv.y, ay) + bb.y, 0.f);
    ((float2*)(out + (size_t)node * HID))[lane] = r;
}

// ---- final aggregation + relu + head dot W3 (1 warp/node) ------------------
__global__ void k_agg_head(const float* __restrict__ xw,
                           const float* __restrict__ b2,
                           const float* __restrict__ W3,
                           const float* __restrict__ b3,
                           float* __restrict__ out, int n) {
    int node = (blockIdx.x * blockDim.x + threadIdx.x) >> 5;
    int lane = threadIdx.x & 31;
    if (node >= n) return;
    float ax = 0.f, ay = 0.f;
    agg_body(xw, node, lane, ax, ay);
    float ds = g_dis[node];
    float d2 = ds * ds;
    float2 xv = __ldg((const float2*)(xw + (size_t)node * HID) + lane);
    float2 bb = __ldg((const float2*)b2 + lane);
    float h0 = fmaxf(fmaf(d2, xv.x, ax) + bb.x, 0.f);
    float h1 = fmaxf(fmaf(d2, xv.y, ay) + bb.y, 0.f);
    float2 w = __ldg((const float2*)W3 + lane);
    float sum = fmaf(h0, w.x, h1 * w.y);
#pragma unroll
    for (int off = 16; off; off >>= 1)
        sum += __shfl_xor_sync(0xffffffffu, sum, off);
    if (lane == 0) out[node] = sum + b3[0];
}

extern "C" void kernel_launch(void* const* d_in, const int* in_sizes, int n_in,
                              void* d_out, int out_size) {
    const float* x   = (const float*)d_in[0];
    const int*   ei  = (const int*)d_in[1];       // int32 (JAX x64 disabled)
    const float* ew  = (const float*)d_in[2];
    // d_in[3] = batch (unused)
    const float* W1  = (const float*)d_in[4];
    const float* b1  = (const float*)d_in[5];
    const float* W2  = (const float*)d_in[6];
    const float* b2  = (const float*)d_in[7];
    const float* W3  = (const float*)d_in[8];
    const float* b3  = (const float*)d_in[9];
    float*       out = (float*)d_out;

    const int n = in_sizes[0] / 128;   // 100000
    const int E = in_sizes[1] / 2;     // 1600000
    const int* src = ei;
    const int* dst = ei + E;

    float *dA, *dB;
    cudaGetSymbolAddress((void**)&dA, g_bufA);
    cudaGetSymbolAddress((void**)&dB, g_bufB);

    const int TB = 256;
    const int NB = (n + SCAN_CHUNK - 1) / SCAN_CHUNK;
    const int GB = (n + 63) / 64;                 // gemm blocks (64 rows each)

    // single stream; gemm128 4th (ncu profiles launch #4)
    k_zero_dc<<<(n + TB - 1) / TB, TB>>>(n);                      // 1
    k_deg_hist<<<(E + TB - 1) / TB, TB>>>(dst, ew, E);            // 2
    k_scan1<<<NB, 1024>>>(n);                                     // 3
    k_gemm<128><<<GB, TB>>>(x, W1, dA, n);                        // 4  <- profiled
    k_scan2<<<1, 1024>>>(NB, n, E);                               // 5
    k_scan3<<<(n + TB - 1) / TB, TB>>>(n);                        // 6
    k_scatter<<<(E + TB - 1) / TB, TB>>>(src, dst, ew, E);        // 7
    k_agg_relu<<<(n * 32 + TB - 1) / TB, TB>>>(dA, b1, dB, n);    // 8
    k_gemm<64><<<GB, TB>>>(dB, W2, dA, n);                        // 9
    k_agg_head<<<(n * 32 + TB - 1) / TB, TB>>>(dA, b2, W3, b3, out, n); // 10
}